// round 6
// baseline (speedup 1.0000x reference)
#include <cuda_runtime.h>

#define H      512
#define NC     64
#define NS     5
#define NQ     15
#define NROWS  1280

__device__ float g_att[NROWS * H];

__device__ __forceinline__ float tanh_approx(float x) {
    float y;
    asm("tanh.approx.f32 %0, %1;" : "=f"(y) : "f"(x));
    return y;
}

// ---------------------------------------------------------------------------
// Kernel 1 (FROZEN, ~10-14us): g_att = X @ W^T + b
// ---------------------------------------------------------------------------
__global__ __launch_bounds__(128) void gemm_xwt(const float* __restrict__ X,
                                                const float* __restrict__ W,
                                                const float* __restrict__ bias) {
    __shared__ float As[16][68];
    __shared__ float Bs[16][36];
    const int t  = threadIdx.x;
    const int tx = t & 7;
    const int ty = t >> 3;
    const int m0 = blockIdx.y * 64;
    const int n0 = blockIdx.x * 32;
    const int lr = t >> 2;
    const int lk = (t & 3) << 2;

    float acc[4][4] = {};

    for (int kk = 0; kk < H; kk += 16) {
        float4 a0 = *(const float4*)&X[(m0 + lr) * H + kk + lk];
        float4 a1 = *(const float4*)&X[(m0 + lr + 32) * H + kk + lk];
        float4 bv = *(const float4*)&W[(n0 + lr) * H + kk + lk];
        As[lk + 0][lr] = a0.x; As[lk + 1][lr] = a0.y;
        As[lk + 2][lr] = a0.z; As[lk + 3][lr] = a0.w;
        As[lk + 0][lr + 32] = a1.x; As[lk + 1][lr + 32] = a1.y;
        As[lk + 2][lr + 32] = a1.z; As[lk + 3][lr + 32] = a1.w;
        Bs[lk + 0][lr] = bv.x; Bs[lk + 1][lr] = bv.y;
        Bs[lk + 2][lr] = bv.z; Bs[lk + 3][lr] = bv.w;
        __syncthreads();
        #pragma unroll
        for (int k = 0; k < 16; k++) {
            float4 a4 = *(const float4*)&As[k][ty << 2];
            float4 b4 = *(const float4*)&Bs[k][tx << 2];
            float ar[4] = {a4.x, a4.y, a4.z, a4.w};
            float br[4] = {b4.x, b4.y, b4.z, b4.w};
            #pragma unroll
            for (int i = 0; i < 4; i++)
                #pragma unroll
                for (int j = 0; j < 4; j++)
                    acc[i][j] = fmaf(ar[i], br[j], acc[i][j]);
        }
        __syncthreads();
    }

    #pragma unroll
    for (int i = 0; i < 4; i++) {
        const int r = m0 + (ty << 2) + i;
        #pragma unroll
        for (int j = 0; j < 4; j++) {
            const int n = n0 + (tx << 2) + j;
            g_att[r * H + n] = acc[i][j] + bias[n];
        }
    }
}

// ---------------------------------------------------------------------------
// Chunk worker: J queries (J=2 main, J=1 tail) for one (query-class, class c).
// Support slices register-cached per h-slice, reused across the J queries.
// ---------------------------------------------------------------------------
template <int J>
__device__ __forceinline__ void process_chunk(
    const float4* __restrict__ attv, const float4* __restrict__ xv,
    const float4* __restrict__ sA, const float4* __restrict__ sS,
    float* __restrict__ out, int c, int qc, int j0, int lane)
{
    // ---- scores ----
    float acc[J][NS];
    #pragma unroll
    for (int j = 0; j < J; j++)
        #pragma unroll
        for (int s = 0; s < NS; s++) acc[j][s] = 0.f;

    #pragma unroll
    for (int i = 0; i < 4; i++) {
        float4 b[NS];
        #pragma unroll
        for (int s = 0; s < NS; s++) b[s] = sA[s * 128 + lane + i * 32];
        #pragma unroll
        for (int j = 0; j < J; j++) {
            const int row = qc * 20 + NS + j0 + j;
            const float4 a = attv[row * 128 + lane + i * 32];
            #pragma unroll
            for (int s = 0; s < NS; s++) {
                acc[j][s] += tanh_approx(a.x * b[s].x);
                acc[j][s] += tanh_approx(a.y * b[s].y);
                acc[j][s] += tanh_approx(a.z * b[s].z);
                acc[j][s] += tanh_approx(a.w * b[s].w);
            }
        }
    }
    #pragma unroll
    for (int j = 0; j < J; j++)
        #pragma unroll
        for (int s = 0; s < NS; s++)
            #pragma unroll
            for (int o = 16; o > 0; o >>= 1)
                acc[j][s] += __shfl_xor_sync(0xffffffffu, acc[j][s], o);

    // ---- softmax over s ----
    #pragma unroll
    for (int j = 0; j < J; j++) {
        float m = acc[j][0];
        #pragma unroll
        for (int s = 1; s < NS; s++) m = fmaxf(m, acc[j][s]);
        float sum = 0.f;
        #pragma unroll
        for (int s = 0; s < NS; s++) { acc[j][s] = __expf(acc[j][s] - m); sum += acc[j][s]; }
        const float inv = __fdividef(1.0f, sum);
        #pragma unroll
        for (int s = 0; s < NS; s++) acc[j][s] *= inv;
    }

    // ---- proto & dist ----
    float d[J];
    #pragma unroll
    for (int j = 0; j < J; j++) d[j] = 0.f;

    #pragma unroll
    for (int i = 0; i < 4; i++) {
        float4 sv[NS];
        #pragma unroll
        for (int s = 0; s < NS; s++) sv[s] = sS[s * 128 + lane + i * 32];
        #pragma unroll
        for (int j = 0; j < J; j++) {
            const int row = qc * 20 + NS + j0 + j;
            const float4 qv = xv[row * 128 + lane + i * 32];
            float px = 0.f, py = 0.f, pz = 0.f, pw = 0.f;
            #pragma unroll
            for (int s = 0; s < NS; s++) {
                px = fmaf(acc[j][s], sv[s].x, px);
                py = fmaf(acc[j][s], sv[s].y, py);
                pz = fmaf(acc[j][s], sv[s].z, pz);
                pw = fmaf(acc[j][s], sv[s].w, pw);
            }
            const float dx = px - qv.x, dy = py - qv.y;
            const float dz = pz - qv.z, dw = pw - qv.w;
            d[j] += dx * dx + dy * dy + dz * dz + dw * dw;
        }
    }
    #pragma unroll
    for (int j = 0; j < J; j++) {
        #pragma unroll
        for (int o = 16; o > 0; o >>= 1)
            d[j] += __shfl_xor_sync(0xffffffffu, d[j], o);
        if (lane == 0)
            out[(qc * NQ + j0 + j) * NC + c] = d[j];
    }
}

// ---------------------------------------------------------------------------
// Kernel 2: grid (64, 8), 256 threads, 128-reg cap (2 blocks/SM, 16 warps).
// Chunk-of-2 queries: LDS traffic halved vs chunk-1 while fitting 128 regs.
// ---------------------------------------------------------------------------
__global__ __launch_bounds__(256, 2) void proto_attn(const float* __restrict__ X,
                                                     float* __restrict__ out) {
    const int c    = blockIdx.x;
    const int qb   = blockIdx.y;
    const int t    = threadIdx.x;
    const int warp = t >> 5;
    const int lane = t & 31;

    __shared__ float4 sA[NS * 128];
    __shared__ float4 sS[NS * 128];

    const float4* attv = (const float4*)g_att;
    const float4* xv   = (const float4*)X;

    for (int i = t; i < NS * 128; i += 256) {
        const int s   = i >> 7;
        const int off = i & 127;
        const int row = c * 20 + s;
        sA[i] = attv[row * 128 + off];
        sS[i] = xv[row * 128 + off];
    }
    __syncthreads();

    const int qc = qb * 8 + warp;

    #pragma unroll 1
    for (int chunk = 0; chunk < 7; chunk++)
        process_chunk<2>(attv, xv, sA, sS, out, c, qc, chunk * 2, lane);
    process_chunk<1>(attv, xv, sA, sS, out, c, qc, 14, lane);
}

extern "C" void kernel_launch(void* const* d_in, const int* in_sizes, int n_in,
                              void* d_out, int out_size) {
    const float* x = (const float*)d_in[0];
    const float* W = (const float*)d_in[1];
    const float* b = (const float*)d_in[2];
    float* out = (float*)d_out;

    gemm_xwt<<<dim3(H / 32, NROWS / 64), 128>>>(x, W, b);
    proto_attn<<<dim3(NC, 8), 256>>>(x, out);
}

// round 7
// speedup vs baseline: 1.0255x; 1.0255x over previous
#include <cuda_runtime.h>

#define H      512
#define NC     64
#define NS     5
#define NQ     15
#define NROWS  1280

__device__ float g_att[NROWS * H];

__device__ __forceinline__ float tanh_approx(float x) {
    float y;
    asm("tanh.approx.f32 %0, %1;" : "=f"(y) : "f"(x));
    return y;
}

// ---------------------------------------------------------------------------
// Kernel 1 (FROZEN): g_att = X @ W^T + b
// 64(m) x 32(n) tile, 128 threads, 4x4 micro-tile, BK=16.
// ---------------------------------------------------------------------------
__global__ __launch_bounds__(128) void gemm_xwt(const float* __restrict__ X,
                                                const float* __restrict__ W,
                                                const float* __restrict__ bias) {
    __shared__ float As[16][68];
    __shared__ float Bs[16][36];
    const int t  = threadIdx.x;
    const int tx = t & 7;
    const int ty = t >> 3;
    const int m0 = blockIdx.y * 64;
    const int n0 = blockIdx.x * 32;
    const int lr = t >> 2;
    const int lk = (t & 3) << 2;

    float acc[4][4] = {};

    for (int kk = 0; kk < H; kk += 16) {
        float4 a0 = *(const float4*)&X[(m0 + lr) * H + kk + lk];
        float4 a1 = *(const float4*)&X[(m0 + lr + 32) * H + kk + lk];
        float4 bv = *(const float4*)&W[(n0 + lr) * H + kk + lk];
        As[lk + 0][lr] = a0.x; As[lk + 1][lr] = a0.y;
        As[lk + 2][lr] = a0.z; As[lk + 3][lr] = a0.w;
        As[lk + 0][lr + 32] = a1.x; As[lk + 1][lr + 32] = a1.y;
        As[lk + 2][lr + 32] = a1.z; As[lk + 3][lr + 32] = a1.w;
        Bs[lk + 0][lr] = bv.x; Bs[lk + 1][lr] = bv.y;
        Bs[lk + 2][lr] = bv.z; Bs[lk + 3][lr] = bv.w;
        __syncthreads();
        #pragma unroll
        for (int k = 0; k < 16; k++) {
            float4 a4 = *(const float4*)&As[k][ty << 2];
            float4 b4 = *(const float4*)&Bs[k][tx << 2];
            float ar[4] = {a4.x, a4.y, a4.z, a4.w};
            float br[4] = {b4.x, b4.y, b4.z, b4.w};
            #pragma unroll
            for (int i = 0; i < 4; i++)
                #pragma unroll
                for (int j = 0; j < 4; j++)
                    acc[i][j] = fmaf(ar[i], br[j], acc[i][j]);
        }
        __syncthreads();
    }

    #pragma unroll
    for (int i = 0; i < 4; i++) {
        const int r = m0 + (ty << 2) + i;
        #pragma unroll
        for (int j = 0; j < 4; j++) {
            const int n = n0 + (tx << 2) + j;
            g_att[r * H + n] = acc[i][j] + bias[n];
        }
    }
}

// ---------------------------------------------------------------------------
// Kernel 2: fused scores -> softmax -> proto -> dists.
// Chunk-1 structure (best measured: R2), occupancy raised to 3 blocks/SM
// (24 warps) via an ~80-reg cap — MUFU (tanh) is the binding pipe; more
// warps hide its 16-cyc latency. Live set ~40 regs, no spill expected.
// ---------------------------------------------------------------------------
__global__ __launch_bounds__(256, 3) void proto_attn(const float* __restrict__ X,
                                                     float* __restrict__ out) {
    const int c    = blockIdx.x;
    const int qb   = blockIdx.y;
    const int t    = threadIdx.x;
    const int warp = t >> 5;
    const int lane = t & 31;

    __shared__ float4 sA[NS * 128];   // s_att rows of class c
    __shared__ float4 sS[NS * 128];   // raw support rows of class c

    const float4* attv = (const float4*)g_att;
    const float4* xv   = (const float4*)X;

    for (int i = t; i < NS * 128; i += 256) {
        const int s   = i >> 7;
        const int off = i & 127;
        const int row = c * 20 + s;
        sA[i] = attv[row * 128 + off];
        sS[i] = xv[row * 128 + off];
    }
    __syncthreads();

    const int qc = qb * 8 + warp;

    for (int j = 0; j < NQ; j++) {
        const int row = qc * 20 + NS + j;
        const float4* qa = attv + row * 128;

        float acc[NS] = {0.f, 0.f, 0.f, 0.f, 0.f};
        #pragma unroll
        for (int i = 0; i < 4; i++) {
            const float4 a = qa[lane + i * 32];
            #pragma unroll
            for (int s = 0; s < NS; s++) {
                const float4 b = sA[s * 128 + lane + i * 32];
                acc[s] += tanh_approx(a.x * b.x);
                acc[s] += tanh_approx(a.y * b.y);
                acc[s] += tanh_approx(a.z * b.z);
                acc[s] += tanh_approx(a.w * b.w);
            }
        }
        #pragma unroll
        for (int s = 0; s < NS; s++) {
            #pragma unroll
            for (int o = 16; o > 0; o >>= 1)
                acc[s] += __shfl_xor_sync(0xffffffffu, acc[s], o);
        }

        // softmax over the 5 support scores
        float m = acc[0];
        #pragma unroll
        for (int s = 1; s < NS; s++) m = fmaxf(m, acc[s]);
        float w[NS];
        float sum = 0.f;
        #pragma unroll
        for (int s = 0; s < NS; s++) { w[s] = __expf(acc[s] - m); sum += w[s]; }
        const float inv = __fdividef(1.0f, sum);
        #pragma unroll
        for (int s = 0; s < NS; s++) w[s] *= inv;

        // proto & dist
        const float4* qx = xv + row * 128;
        float d = 0.f;
        #pragma unroll
        for (int i = 0; i < 4; i++) {
            const float4 qv = qx[lane + i * 32];
            float px = 0.f, py = 0.f, pz = 0.f, pw = 0.f;
            #pragma unroll
            for (int s = 0; s < NS; s++) {
                const float4 sv = sS[s * 128 + lane + i * 32];
                px = fmaf(w[s], sv.x, px);
                py = fmaf(w[s], sv.y, py);
                pz = fmaf(w[s], sv.z, pz);
                pw = fmaf(w[s], sv.w, pw);
            }
            const float dx = px - qv.x, dy = py - qv.y;
            const float dz = pz - qv.z, dw = pw - qv.w;
            d += dx * dx + dy * dy + dz * dz + dw * dw;
        }
        #pragma unroll
        for (int o = 16; o > 0; o >>= 1)
            d += __shfl_xor_sync(0xffffffffu, d, o);

        if (lane == 0) {
            const int q = qc * NQ + j;
            out[q * NC + c] = d;
        }
    }
}

extern "C" void kernel_launch(void* const* d_in, const int* in_sizes, int n_in,
                              void* d_out, int out_size) {
    const float* x = (const float*)d_in[0];
    const float* W = (const float*)d_in[1];
    const float* b = (const float*)d_in[2];
    float* out = (float*)d_out;

    gemm_xwt<<<dim3(H / 32, NROWS / 64), 128>>>(x, W, b);
    proto_attn<<<dim3(NC, 8), 256>>>(x, out);
}

// round 8
// speedup vs baseline: 1.1958x; 1.1661x over previous
#include <cuda_runtime.h>

#define H      512
#define NC     64
#define NS     5
#define NQ     15
#define NROWS  1280

__device__ float g_att[NROWS * H];

__device__ __forceinline__ float tanh_approx(float x) {
    float y;
    asm("tanh.approx.f32 %0, %1;" : "=f"(y) : "f"(x));
    return y;
}

// ---------------------------------------------------------------------------
// Kernel 1 (FROZEN): g_att = X @ W^T + b
// 64(m) x 32(n) tile, 128 threads, 4x4 micro-tile, BK=16.
// ---------------------------------------------------------------------------
__global__ __launch_bounds__(128) void gemm_xwt(const float* __restrict__ X,
                                                const float* __restrict__ W,
                                                const float* __restrict__ bias) {
    __shared__ float As[16][68];
    __shared__ float Bs[16][36];
    const int t  = threadIdx.x;
    const int tx = t & 7;
    const int ty = t >> 3;
    const int m0 = blockIdx.y * 64;
    const int n0 = blockIdx.x * 32;
    const int lr = t >> 2;
    const int lk = (t & 3) << 2;

    float acc[4][4] = {};

    for (int kk = 0; kk < H; kk += 16) {
        float4 a0 = *(const float4*)&X[(m0 + lr) * H + kk + lk];
        float4 a1 = *(const float4*)&X[(m0 + lr + 32) * H + kk + lk];
        float4 bv = *(const float4*)&W[(n0 + lr) * H + kk + lk];
        As[lk + 0][lr] = a0.x; As[lk + 1][lr] = a0.y;
        As[lk + 2][lr] = a0.z; As[lk + 3][lr] = a0.w;
        As[lk + 0][lr + 32] = a1.x; As[lk + 1][lr + 32] = a1.y;
        As[lk + 2][lr + 32] = a1.z; As[lk + 3][lr + 32] = a1.w;
        Bs[lk + 0][lr] = bv.x; Bs[lk + 1][lr] = bv.y;
        Bs[lk + 2][lr] = bv.z; Bs[lk + 3][lr] = bv.w;
        __syncthreads();
        #pragma unroll
        for (int k = 0; k < 16; k++) {
            float4 a4 = *(const float4*)&As[k][ty << 2];
            float4 b4 = *(const float4*)&Bs[k][tx << 2];
            float ar[4] = {a4.x, a4.y, a4.z, a4.w};
            float br[4] = {b4.x, b4.y, b4.z, b4.w};
            #pragma unroll
            for (int i = 0; i < 4; i++)
                #pragma unroll
                for (int j = 0; j < 4; j++)
                    acc[i][j] = fmaf(ar[i], br[j], acc[i][j]);
        }
        __syncthreads();
    }

    #pragma unroll
    for (int i = 0; i < 4; i++) {
        const int r = m0 + (ty << 2) + i;
        #pragma unroll
        for (int j = 0; j < 4; j++) {
            const int n = n0 + (tx << 2) + j;
            g_att[r * H + n] = acc[i][j] + bias[n];
        }
    }
}

// ---------------------------------------------------------------------------
// Kernel 2: EXACT round-2 structure (measured best: 68.4us) — chunk-1 per
// query, 8 warps/block, grid (64, 8). (256, 2) pins the 128-reg allocation
// that structure naturally compiled to.
// ---------------------------------------------------------------------------
__global__ __launch_bounds__(256, 2) void proto_attn(const float* __restrict__ X,
                                                     float* __restrict__ out) {
    const int c    = blockIdx.x;
    const int qb   = blockIdx.y;
    const int t    = threadIdx.x;
    const int warp = t >> 5;
    const int lane = t & 31;

    __shared__ float4 sA[NS * 128];   // s_att rows of class c
    __shared__ float4 sS[NS * 128];   // raw support rows of class c

    const float4* attv = (const float4*)g_att;
    const float4* xv   = (const float4*)X;

    for (int i = t; i < NS * 128; i += 256) {
        const int s   = i >> 7;
        const int off = i & 127;
        const int row = c * 20 + s;
        sA[i] = attv[row * 128 + off];
        sS[i] = xv[row * 128 + off];
    }
    __syncthreads();

    const int qc = qb * 8 + warp;

    for (int j = 0; j < NQ; j++) {
        const int row = qc * 20 + NS + j;
        const float4* qa = attv + row * 128;

        float acc[NS] = {0.f, 0.f, 0.f, 0.f, 0.f};
        #pragma unroll
        for (int i = 0; i < 4; i++) {
            const float4 a = qa[lane + i * 32];
            #pragma unroll
            for (int s = 0; s < NS; s++) {
                const float4 b = sA[s * 128 + lane + i * 32];
                acc[s] += tanh_approx(a.x * b.x);
                acc[s] += tanh_approx(a.y * b.y);
                acc[s] += tanh_approx(a.z * b.z);
                acc[s] += tanh_approx(a.w * b.w);
            }
        }
        #pragma unroll
        for (int s = 0; s < NS; s++) {
            #pragma unroll
            for (int o = 16; o > 0; o >>= 1)
                acc[s] += __shfl_xor_sync(0xffffffffu, acc[s], o);
        }

        // softmax over the 5 support scores
        float m = acc[0];
        #pragma unroll
        for (int s = 1; s < NS; s++) m = fmaxf(m, acc[s]);
        float w[NS];
        float sum = 0.f;
        #pragma unroll
        for (int s = 0; s < NS; s++) { w[s] = __expf(acc[s] - m); sum += w[s]; }
        const float inv = __fdividef(1.0f, sum);
        #pragma unroll
        for (int s = 0; s < NS; s++) w[s] *= inv;

        // proto & dist
        const float4* qx = xv + row * 128;
        float d = 0.f;
        #pragma unroll
        for (int i = 0; i < 4; i++) {
            const float4 qv = qx[lane + i * 32];
            float px = 0.f, py = 0.f, pz = 0.f, pw = 0.f;
            #pragma unroll
            for (int s = 0; s < NS; s++) {
                const float4 sv = sS[s * 128 + lane + i * 32];
                px = fmaf(w[s], sv.x, px);
                py = fmaf(w[s], sv.y, py);
                pz = fmaf(w[s], sv.z, pz);
                pw = fmaf(w[s], sv.w, pw);
            }
            const float dx = px - qv.x, dy = py - qv.y;
            const float dz = pz - qv.z, dw = pw - qv.w;
            d += dx * dx + dy * dy + dz * dz + dw * dw;
        }
        #pragma unroll
        for (int o = 16; o > 0; o >>= 1)
            d += __shfl_xor_sync(0xffffffffu, d, o);

        if (lane == 0) {
            const int q = qc * NQ + j;
            out[q * NC + c] = d;
        }
    }
}

extern "C" void kernel_launch(void* const* d_in, const int* in_sizes, int n_in,
                              void* d_out, int out_size) {
    const float* x = (const float*)d_in[0];
    const float* W = (const float*)d_in[1];
    const float* b = (const float*)d_in[2];
    float* out = (float*)d_out;

    gemm_xwt<<<dim3(H / 32, NROWS / 64), 128>>>(x, W, b);
    proto_attn<<<dim3(NC, 8), 256>>>(x, out);
}